// round 1
// baseline (speedup 1.0000x reference)
#include <cuda_runtime.h>
#include <math.h>

#define Bsz 8
#define Sseq 4096
#define Hdim 1024
#define NHEAD 16
#define HDm 64
#define BSROWS (Bsz * Sseq)          // 32768
#define EPS_ATTN 1e-6f
#define EPS_LN 1e-12f

// ---------------- scratch (device globals; no allocation allowed) -----------
__device__ float g_q[(size_t)BSROWS * Hdim];     // q, later reused as hs
__device__ float g_k[(size_t)BSROWS * Hdim];     // k, later reused as ctx
__device__ float g_v[(size_t)BSROWS * Hdim];     // v
__device__ float g_kv[Bsz * NHEAD * HDm * HDm];  // kv state [bh][m][d]
__device__ float g_ksum[Bsz * NHEAD * HDm];      // sum_s k  [bh][d]

// ---------------- generic SGEMM: C = A[M,K] @ W[N,K]^T + bias (+resid)(+act)
// 128x128 tile, k-tile 8, 256 threads, 8x8 microtile.
__global__ __launch_bounds__(256, 2)
void sgemm_nt(const float* __restrict__ A, const float* __restrict__ W,
              const float* __restrict__ bias, const float* __restrict__ resid,
              float* __restrict__ C, int M, int N, int K, int act)
{
    __shared__ float As[8][128];
    __shared__ float Ws[8][128];

    const int tid  = threadIdx.x;
    const int row0 = blockIdx.y * 128;
    const int col0 = blockIdx.x * 128;

    const int lrow = tid >> 1;          // 0..127
    const int lk   = (tid & 1) << 2;    // 0 or 4

    const float* Ap = A + (size_t)(row0 + lrow) * K + lk;
    const float* Wp = W + (size_t)(col0 + lrow) * K + lk;

    const int tx = tid & 15;            // col microtile
    const int ty = tid >> 4;            // row microtile

    float acc[8][8];
    #pragma unroll
    for (int i = 0; i < 8; i++)
        #pragma unroll
        for (int j = 0; j < 8; j++) acc[i][j] = 0.f;

    for (int kt = 0; kt < K; kt += 8) {
        float4 a4 = *(const float4*)(Ap + kt);
        float4 w4 = *(const float4*)(Wp + kt);
        __syncthreads();
        As[lk + 0][lrow] = a4.x; As[lk + 1][lrow] = a4.y;
        As[lk + 2][lrow] = a4.z; As[lk + 3][lrow] = a4.w;
        Ws[lk + 0][lrow] = w4.x; Ws[lk + 1][lrow] = w4.y;
        Ws[lk + 2][lrow] = w4.z; Ws[lk + 3][lrow] = w4.w;
        __syncthreads();

        #pragma unroll
        for (int kk = 0; kk < 8; kk++) {
            float4 a0 = *(const float4*)&As[kk][ty * 8];
            float4 a1 = *(const float4*)&As[kk][ty * 8 + 4];
            float4 w0 = *(const float4*)&Ws[kk][tx * 8];
            float4 w1 = *(const float4*)&Ws[kk][tx * 8 + 4];
            float a[8] = {a0.x, a0.y, a0.z, a0.w, a1.x, a1.y, a1.z, a1.w};
            float w[8] = {w0.x, w0.y, w0.z, w0.w, w1.x, w1.y, w1.z, w1.w};
            #pragma unroll
            for (int i = 0; i < 8; i++)
                #pragma unroll
                for (int j = 0; j < 8; j++)
                    acc[i][j] = fmaf(a[i], w[j], acc[i][j]);
        }
    }

    #pragma unroll
    for (int i = 0; i < 8; i++) {
        const int row = row0 + ty * 8 + i;
        float* Crow = C + (size_t)row * N + col0 + tx * 8;
        const float* Rrow = resid ? (resid + (size_t)row * N + col0 + tx * 8) : nullptr;
        #pragma unroll
        for (int j = 0; j < 8; j++) {
            float val = acc[i][j] + bias[col0 + tx * 8 + j];
            if (Rrow) val += Rrow[j];
            if (act) val = (val > 0.f) ? (val + 1.f) : expf(val);  // elu(x)+1
            Crow[j] = val;
        }
    }
}

// ---------------- kv state + ksum:  kv[bh][m][d] = sum_s v[s][m] * k[s][d]
__global__ __launch_bounds__(256)
void kv_accum(const float* __restrict__ k, const float* __restrict__ v,
              float* __restrict__ kv, float* __restrict__ ksum)
{
    const int bh = blockIdx.x;               // 0..127
    const int b  = bh / NHEAD, h = bh % NHEAD;
    const int s0 = blockIdx.y * (Sseq / 8);  // 512-token chunk

    __shared__ float ks[4][HDm];
    __shared__ float vs[4][HDm];

    const int tid = threadIdx.x;
    const int tx = tid & 15, ty = tid >> 4;
    const int d0 = tx * 4, m0 = ty * 4;
    const int tt = tid >> 6;   // token within group of 4
    const int cc = tid & 63;   // column

    float acc[4][4];
    #pragma unroll
    for (int m = 0; m < 4; m++)
        #pragma unroll
        for (int d = 0; d < 4; d++) acc[m][d] = 0.f;
    float kloc = 0.f;

    for (int s = s0; s < s0 + Sseq / 8; s += 4) {
        __syncthreads();
        const size_t base = ((size_t)(b * Sseq + s + tt)) * Hdim + h * HDm + cc;
        ks[tt][cc] = k[base];
        vs[tt][cc] = v[base];
        __syncthreads();

        #pragma unroll
        for (int t = 0; t < 4; t++) {
            float kk4[4] = {ks[t][d0], ks[t][d0 + 1], ks[t][d0 + 2], ks[t][d0 + 3]};
            float vv4[4] = {vs[t][m0], vs[t][m0 + 1], vs[t][m0 + 2], vs[t][m0 + 3]};
            #pragma unroll
            for (int m = 0; m < 4; m++)
                #pragma unroll
                for (int d = 0; d < 4; d++)
                    acc[m][d] = fmaf(vv4[m], kk4[d], acc[m][d]);
        }
        if (tid < HDm)
            kloc += ks[0][tid] + ks[1][tid] + ks[2][tid] + ks[3][tid];
    }

    float* kvp = kv + (size_t)bh * HDm * HDm;
    #pragma unroll
    for (int m = 0; m < 4; m++)
        #pragma unroll
        for (int d = 0; d < 4; d++)
            atomicAdd(&kvp[(m0 + m) * HDm + (d0 + d)], acc[m][d]);
    if (tid < HDm) atomicAdd(&ksum[bh * HDm + tid], kloc);
}

// ---------------- ctx[s][m] = (q[s] . kv[m,:]) / (q[s] . (ksum+eps))
__global__ __launch_bounds__(256)
void ctx_kernel(const float* __restrict__ q, const float* __restrict__ kv,
                const float* __restrict__ ksum, float* __restrict__ ctx)
{
    const int bh = blockIdx.x;
    const int b = bh / NHEAD, h = bh % NHEAD;
    const int s0 = blockIdx.y * 128;

    __shared__ float kvT[HDm][HDm];   // kvT[d][m]
    __shared__ float kse[HDm];
    __shared__ float qsh[4][HDm];

    const int tid = threadIdx.x;
    const float* kvp = kv + (size_t)bh * HDm * HDm;
    for (int i = tid; i < HDm * HDm; i += 256)
        kvT[i & 63][i >> 6] = kvp[i];
    if (tid < HDm) kse[tid] = ksum[bh * HDm + tid] + EPS_ATTN;
    __syncthreads();

    const int ty = tid >> 6;   // token within group of 4
    const int m  = tid & 63;

    for (int g = 0; g < 32; g++) {
        const int s = s0 + g * 4 + ty;
        const size_t base = ((size_t)(b * Sseq + s)) * Hdim + h * HDm;
        qsh[ty][m] = q[base + m];
        __syncthreads();

        float dot = 0.f, acc = 0.f;
        #pragma unroll 8
        for (int d = 0; d < HDm; d++) {
            const float qd = qsh[ty][d];
            dot = fmaf(qd, kse[d], dot);
            acc = fmaf(qd, kvT[d][m], acc);
        }
        ctx[base + m] = acc / dot;
        __syncthreads();
    }
}

// ---------------- LayerNorm over rows of 1024
__global__ __launch_bounds__(256)
void ln_kernel(const float* __restrict__ hs, const float* __restrict__ gamma,
               const float* __restrict__ beta, float* __restrict__ out)
{
    const int row = blockIdx.x;
    const int tid = threadIdx.x;
    const float4 v = ((const float4*)(hs + (size_t)row * Hdim))[tid];

    float s  = v.x + v.y + v.z + v.w;
    float sq = v.x * v.x + v.y * v.y + v.z * v.z + v.w * v.w;
    #pragma unroll
    for (int o = 16; o > 0; o >>= 1) {
        s  += __shfl_xor_sync(0xFFFFFFFFu, s, o);
        sq += __shfl_xor_sync(0xFFFFFFFFu, sq, o);
    }
    __shared__ float rs[8], rq[8];
    const int wid = tid >> 5, lane = tid & 31;
    if (lane == 0) { rs[wid] = s; rq[wid] = sq; }
    __syncthreads();
    float sum = 0.f, sumq = 0.f;
    #pragma unroll
    for (int i = 0; i < 8; i++) { sum += rs[i]; sumq += rq[i]; }

    const float mu   = sum * (1.f / Hdim);
    const float var  = sumq * (1.f / Hdim) - mu * mu;
    const float rstd = rsqrtf(var + EPS_LN);

    const float4 g4 = ((const float4*)gamma)[tid];
    const float4 b4 = ((const float4*)beta)[tid];
    float4 o;
    o.x = (v.x - mu) * rstd * g4.x + b4.x;
    o.y = (v.y - mu) * rstd * g4.y + b4.y;
    o.z = (v.z - mu) * rstd * g4.z + b4.z;
    o.w = (v.w - mu) * rstd * g4.w + b4.w;
    ((float4*)(out + (size_t)row * Hdim))[tid] = o;
}

__global__ void zero_kernel(float* p, int n)
{
    const int i = blockIdx.x * blockDim.x + threadIdx.x;
    if (i < n) p[i] = 0.f;
}

// ---------------- launch ----------------------------------------------------
extern "C" void kernel_launch(void* const* d_in, const int* in_sizes, int n_in,
                              void* d_out, int out_size)
{
    const float* x     = (const float*)d_in[0];
    // d_in[1] = attention_mask (all zeros, unused by the reference math)
    const float* Wq    = (const float*)d_in[2];
    const float* bq    = (const float*)d_in[3];
    const float* Wk    = (const float*)d_in[4];
    const float* bk    = (const float*)d_in[5];
    const float* Wv    = (const float*)d_in[6];
    const float* bv    = (const float*)d_in[7];
    const float* Wd    = (const float*)d_in[8];
    const float* bd    = (const float*)d_in[9];
    const float* gamma = (const float*)d_in[10];
    const float* beta  = (const float*)d_in[11];
    float* out = (float*)d_out;

    float *q, *k, *v, *kv, *ksum;
    cudaGetSymbolAddress((void**)&q,    g_q);
    cudaGetSymbolAddress((void**)&k,    g_k);
    cudaGetSymbolAddress((void**)&v,    g_v);
    cudaGetSymbolAddress((void**)&kv,   g_kv);
    cudaGetSymbolAddress((void**)&ksum, g_ksum);

    const dim3 gemm_grid(Hdim / 128, BSROWS / 128);  // (8, 256)
    const dim3 gemm_block(256);

    // QKV projections (+ elu+1 on q,k)
    sgemm_nt<<<gemm_grid, gemm_block>>>(x, Wq, bq, nullptr, q, BSROWS, Hdim, Hdim, 1);
    sgemm_nt<<<gemm_grid, gemm_block>>>(x, Wk, bk, nullptr, k, BSROWS, Hdim, Hdim, 1);
    sgemm_nt<<<gemm_grid, gemm_block>>>(x, Wv, bv, nullptr, v, BSROWS, Hdim, Hdim, 0);

    // zero kv state (graph replays must be deterministic)
    const int kvn = Bsz * NHEAD * HDm * HDm;
    const int ksn = Bsz * NHEAD * HDm;
    zero_kernel<<<(kvn + 255) / 256, 256>>>(kv, kvn);
    zero_kernel<<<(ksn + 255) / 256, 256>>>(ksum, ksn);

    // kv state + ksum
    kv_accum<<<dim3(Bsz * NHEAD, 8), 256>>>(k, v, kv, ksum);

    // ctx (reuses g_k — k is dead after kv_accum)
    ctx_kernel<<<dim3(Bsz * NHEAD, Sseq / 128), 256>>>(q, kv, ksum, k);

    // output projection + bias + residual (hs reuses g_q — q is dead now)
    sgemm_nt<<<gemm_grid, gemm_block>>>(k, Wd, bd, x, q, BSROWS, Hdim, Hdim, 0);

    // LayerNorm
    ln_kernel<<<BSROWS, 256>>>(q, gamma, beta, out);
}

// round 2
// speedup vs baseline: 2.1303x; 2.1303x over previous
#include <cuda_runtime.h>
#include <cstdint>
#include <math.h>

#define Bsz 8
#define Sseq 4096
#define Hdim 1024
#define NHEAD 16
#define HDm 64
#define BSROWS (Bsz * Sseq)          // 32768
#define EPS_ATTN 1e-6f
#define EPS_LN 1e-12f

// ---------------- scratch (device globals; no allocation allowed) -----------
__device__ float g_q[(size_t)BSROWS * Hdim];     // q, later reused as hs
__device__ float g_k[(size_t)BSROWS * Hdim];     // k, later reused as ctx
__device__ float g_v[(size_t)BSROWS * Hdim];     // v
__device__ float g_kv[Bsz * NHEAD * HDm * HDm];  // kv state [bh][m][d]
__device__ float g_ksum[Bsz * NHEAD * HDm];      // sum_s k  [bh][d]

// ---------------- tf32 helpers ----------------------------------------------
__device__ __forceinline__ uint32_t f2tf(float f) {
    uint32_t u;
    asm("cvt.rna.tf32.f32 %0, %1;" : "=r"(u) : "f"(f));
    return u;
}

__device__ __forceinline__ void mma_tf32(float* c, const uint32_t* a, const uint32_t* b) {
    asm volatile(
        "mma.sync.aligned.m16n8k8.row.col.f32.tf32.tf32.f32 "
        "{%0,%1,%2,%3}, {%4,%5,%6,%7}, {%8,%9}, {%0,%1,%2,%3};"
        : "+f"(c[0]), "+f"(c[1]), "+f"(c[2]), "+f"(c[3])
        : "r"(a[0]), "r"(a[1]), "r"(a[2]), "r"(a[3]), "r"(b[0]), "r"(b[1]));
}

// ---------------- TF32 tensor-core SGEMM: C = A[M,K] @ W[N,K]^T + bias ------
// 128x128 tile, BK=16, 8 warps (2x4), each warp 64x32 via 4x4 m16n8k8 frags.
// Smem rows stride 20 floats -> conflict-free fragment gathers.
#define BKt 16
#define LDST 20

__global__ __launch_bounds__(256)
void gemm_tf32(const float* __restrict__ A, const float* __restrict__ W,
               const float* __restrict__ bias, const float* __restrict__ resid,
               float* __restrict__ C, int K, int N, int act)
{
    __shared__ uint32_t As[2][128 * LDST];
    __shared__ uint32_t Ws[2][128 * LDST];

    const int tid  = threadIdx.x;
    const int lane = tid & 31;
    const int wid  = tid >> 5;
    const int wm   = wid & 1;          // warp row (2)
    const int wn   = wid >> 1;         // warp col (4)
    const int row0 = blockIdx.y * 128;
    const int col0 = blockIdx.x * 128;

    const int grow = tid >> 1;         // 0..127: smem row this thread fills
    const int gk   = (tid & 1) * 8;    // k-offset 0 or 8 (two float4)

    const float* Ap = A + (size_t)(row0 + grow) * K + gk;
    const float* Wp = W + (size_t)(col0 + grow) * K + gk;

    float acc[4][4][4] = {};

    const int nt = K / BKt;

    // preload tile 0
    float4 ra0 = *(const float4*)(Ap);
    float4 ra1 = *(const float4*)(Ap + 4);
    float4 rw0 = *(const float4*)(Wp);
    float4 rw1 = *(const float4*)(Wp + 4);
    {
        uint32_t* as = &As[0][grow * LDST + gk];
        as[0] = f2tf(ra0.x); as[1] = f2tf(ra0.y); as[2] = f2tf(ra0.z); as[3] = f2tf(ra0.w);
        as[4] = f2tf(ra1.x); as[5] = f2tf(ra1.y); as[6] = f2tf(ra1.z); as[7] = f2tf(ra1.w);
        uint32_t* ws = &Ws[0][grow * LDST + gk];
        ws[0] = f2tf(rw0.x); ws[1] = f2tf(rw0.y); ws[2] = f2tf(rw0.z); ws[3] = f2tf(rw0.w);
        ws[4] = f2tf(rw1.x); ws[5] = f2tf(rw1.y); ws[6] = f2tf(rw1.z); ws[7] = f2tf(rw1.w);
    }
    __syncthreads();

    for (int kt = 0; kt < nt; kt++) {
        const int buf = kt & 1;
        if (kt + 1 < nt) {
            ra0 = *(const float4*)(Ap + (kt + 1) * BKt);
            ra1 = *(const float4*)(Ap + (kt + 1) * BKt + 4);
            rw0 = *(const float4*)(Wp + (kt + 1) * BKt);
            rw1 = *(const float4*)(Wp + (kt + 1) * BKt + 4);
        }

        #pragma unroll
        for (int kk = 0; kk < BKt; kk += 8) {
            uint32_t af[4][4], bf[4][2];
            const int c = kk + (lane & 3);
            #pragma unroll
            for (int mf = 0; mf < 4; mf++) {
                const int r = wm * 64 + mf * 16 + (lane >> 2);
                af[mf][0] = As[buf][r * LDST + c];
                af[mf][1] = As[buf][(r + 8) * LDST + c];
                af[mf][2] = As[buf][r * LDST + c + 4];
                af[mf][3] = As[buf][(r + 8) * LDST + c + 4];
            }
            #pragma unroll
            for (int nf = 0; nf < 4; nf++) {
                const int n = wn * 32 + nf * 8 + (lane >> 2);
                bf[nf][0] = Ws[buf][n * LDST + c];
                bf[nf][1] = Ws[buf][n * LDST + c + 4];
            }
            #pragma unroll
            for (int mf = 0; mf < 4; mf++)
                #pragma unroll
                for (int nf = 0; nf < 4; nf++)
                    mma_tf32(acc[mf][nf], af[mf], bf[nf]);
        }

        if (kt + 1 < nt) {
            const int nb = buf ^ 1;
            uint32_t* as = &As[nb][grow * LDST + gk];
            as[0] = f2tf(ra0.x); as[1] = f2tf(ra0.y); as[2] = f2tf(ra0.z); as[3] = f2tf(ra0.w);
            as[4] = f2tf(ra1.x); as[5] = f2tf(ra1.y); as[6] = f2tf(ra1.z); as[7] = f2tf(ra1.w);
            uint32_t* ws = &Ws[nb][grow * LDST + gk];
            ws[0] = f2tf(rw0.x); ws[1] = f2tf(rw0.y); ws[2] = f2tf(rw0.z); ws[3] = f2tf(rw0.w);
            ws[4] = f2tf(rw1.x); ws[5] = f2tf(rw1.y); ws[6] = f2tf(rw1.z); ws[7] = f2tf(rw1.w);
            __syncthreads();
        }
    }

    // epilogue: bias (+resid) (+elu+1)
    #pragma unroll
    for (int mf = 0; mf < 4; mf++) {
        #pragma unroll
        for (int nf = 0; nf < 4; nf++) {
            const int r   = row0 + wm * 64 + mf * 16 + (lane >> 2);
            const int cgl = col0 + wn * 32 + nf * 8 + 2 * (lane & 3);
            const float b0 = bias[cgl], b1 = bias[cgl + 1];
            #pragma unroll
            for (int half = 0; half < 2; half++) {
                const int rr = r + half * 8;
                float v0 = acc[mf][nf][half * 2 + 0] + b0;
                float v1 = acc[mf][nf][half * 2 + 1] + b1;
                if (resid) {
                    const float* rp = resid + (size_t)rr * N + cgl;
                    v0 += rp[0];
                    v1 += rp[1];
                }
                if (act) {
                    v0 = (v0 > 0.f) ? (v0 + 1.f) : expf(v0);
                    v1 = (v1 > 0.f) ? (v1 + 1.f) : expf(v1);
                }
                *(float2*)(C + (size_t)rr * N + cgl) = make_float2(v0, v1);
            }
        }
    }
}

// ---------------- kv state + ksum:  kv[bh][m][d] = sum_s v[s][m] * k[s][d]
__global__ __launch_bounds__(256)
void kv_accum(const float* __restrict__ k, const float* __restrict__ v,
              float* __restrict__ kv, float* __restrict__ ksum)
{
    const int bh = blockIdx.x;               // 0..127
    const int b  = bh / NHEAD, h = bh % NHEAD;
    const int s0 = blockIdx.y * (Sseq / 8);  // 512-token chunk

    __shared__ float ks[4][HDm];
    __shared__ float vs[4][HDm];

    const int tid = threadIdx.x;
    const int tx = tid & 15, ty = tid >> 4;
    const int d0 = tx * 4, m0 = ty * 4;
    const int tt = tid >> 6;   // token within group of 4
    const int cc = tid & 63;   // column

    float acc[4][4];
    #pragma unroll
    for (int m = 0; m < 4; m++)
        #pragma unroll
        for (int d = 0; d < 4; d++) acc[m][d] = 0.f;
    float kloc = 0.f;

    for (int s = s0; s < s0 + Sseq / 8; s += 4) {
        __syncthreads();
        const size_t base = ((size_t)(b * Sseq + s + tt)) * Hdim + h * HDm + cc;
        ks[tt][cc] = k[base];
        vs[tt][cc] = v[base];
        __syncthreads();

        #pragma unroll
        for (int t = 0; t < 4; t++) {
            float kk4[4] = {ks[t][d0], ks[t][d0 + 1], ks[t][d0 + 2], ks[t][d0 + 3]};
            float vv4[4] = {vs[t][m0], vs[t][m0 + 1], vs[t][m0 + 2], vs[t][m0 + 3]};
            #pragma unroll
            for (int m = 0; m < 4; m++)
                #pragma unroll
                for (int d = 0; d < 4; d++)
                    acc[m][d] = fmaf(vv4[m], kk4[d], acc[m][d]);
        }
        if (tid < HDm)
            kloc += ks[0][tid] + ks[1][tid] + ks[2][tid] + ks[3][tid];
    }

    float* kvp = kv + (size_t)bh * HDm * HDm;
    #pragma unroll
    for (int m = 0; m < 4; m++)
        #pragma unroll
        for (int d = 0; d < 4; d++)
            atomicAdd(&kvp[(m0 + m) * HDm + (d0 + d)], acc[m][d]);
    if (tid < HDm) atomicAdd(&ksum[bh * HDm + tid], kloc);
}

// ---------------- ctx[s][m] = (q[s] . kv[m,:]) / (q[s] . (ksum+eps))
__global__ __launch_bounds__(256)
void ctx_kernel(const float* __restrict__ q, const float* __restrict__ kv,
                const float* __restrict__ ksum, float* __restrict__ ctx)
{
    const int bh = blockIdx.x;
    const int b = bh / NHEAD, h = bh % NHEAD;
    const int s0 = blockIdx.y * 128;

    __shared__ float kvT[HDm][HDm];   // kvT[d][m]
    __shared__ float kse[HDm];
    __shared__ float qsh[4][HDm];

    const int tid = threadIdx.x;
    const float* kvp = kv + (size_t)bh * HDm * HDm;
    for (int i = tid; i < HDm * HDm; i += 256)
        kvT[i & 63][i >> 6] = kvp[i];
    if (tid < HDm) kse[tid] = ksum[bh * HDm + tid] + EPS_ATTN;
    __syncthreads();

    const int ty = tid >> 6;   // token within group of 4
    const int m  = tid & 63;

    for (int g = 0; g < 32; g++) {
        const int s = s0 + g * 4 + ty;
        const size_t base = ((size_t)(b * Sseq + s)) * Hdim + h * HDm;
        qsh[ty][m] = q[base + m];
        __syncthreads();

        float dot = 0.f, acc = 0.f;
        #pragma unroll 8
        for (int d = 0; d < HDm; d++) {
            const float qd = qsh[ty][d];
            dot = fmaf(qd, kse[d], dot);
            acc = fmaf(qd, kvT[d][m], acc);
        }
        ctx[base + m] = acc / dot;
        __syncthreads();
    }
}

// ---------------- LayerNorm over rows of 1024
__global__ __launch_bounds__(256)
void ln_kernel(const float* __restrict__ hs, const float* __restrict__ gamma,
               const float* __restrict__ beta, float* __restrict__ out)
{
    const int row = blockIdx.x;
    const int tid = threadIdx.x;
    const float4 v = ((const float4*)(hs + (size_t)row * Hdim))[tid];

    float s  = v.x + v.y + v.z + v.w;
    float sq = v.x * v.x + v.y * v.y + v.z * v.z + v.w * v.w;
    #pragma unroll
    for (int o = 16; o > 0; o >>= 1) {
        s  += __shfl_xor_sync(0xFFFFFFFFu, s, o);
        sq += __shfl_xor_sync(0xFFFFFFFFu, sq, o);
    }
    __shared__ float rs[8], rq[8];
    const int wid = tid >> 5, lane = tid & 31;
    if (lane == 0) { rs[wid] = s; rq[wid] = sq; }
    __syncthreads();
    float sum = 0.f, sumq = 0.f;
    #pragma unroll
    for (int i = 0; i < 8; i++) { sum += rs[i]; sumq += rq[i]; }

    const float mu   = sum * (1.f / Hdim);
    const float var  = sumq * (1.f / Hdim) - mu * mu;
    const float rstd = rsqrtf(var + EPS_LN);

    const float4 g4 = ((const float4*)gamma)[tid];
    const float4 b4 = ((const float4*)beta)[tid];
    float4 o;
    o.x = (v.x - mu) * rstd * g4.x + b4.x;
    o.y = (v.y - mu) * rstd * g4.y + b4.y;
    o.z = (v.z - mu) * rstd * g4.z + b4.z;
    o.w = (v.w - mu) * rstd * g4.w + b4.w;
    ((float4*)(out + (size_t)row * Hdim))[tid] = o;
}

__global__ void zero_kernel(float* p, int n)
{
    const int i = blockIdx.x * blockDim.x + threadIdx.x;
    if (i < n) p[i] = 0.f;
}

// ---------------- launch ----------------------------------------------------
extern "C" void kernel_launch(void* const* d_in, const int* in_sizes, int n_in,
                              void* d_out, int out_size)
{
    const float* x     = (const float*)d_in[0];
    // d_in[1] = attention_mask (all zeros, unused by the reference math)
    const float* Wq    = (const float*)d_in[2];
    const float* bq    = (const float*)d_in[3];
    const float* Wk    = (const float*)d_in[4];
    const float* bk    = (const float*)d_in[5];
    const float* Wv    = (const float*)d_in[6];
    const float* bv    = (const float*)d_in[7];
    const float* Wd    = (const float*)d_in[8];
    const float* bd    = (const float*)d_in[9];
    const float* gamma = (const float*)d_in[10];
    const float* beta  = (const float*)d_in[11];
    float* out = (float*)d_out;

    float *q, *k, *v, *kv, *ksum;
    cudaGetSymbolAddress((void**)&q,    g_q);
    cudaGetSymbolAddress((void**)&k,    g_k);
    cudaGetSymbolAddress((void**)&v,    g_v);
    cudaGetSymbolAddress((void**)&kv,   g_kv);
    cudaGetSymbolAddress((void**)&ksum, g_ksum);

    const dim3 gemm_grid(Hdim / 128, BSROWS / 128);  // (8, 256)
    const dim3 gemm_block(256);

    // QKV projections (+ elu+1 on q,k) — TF32 tensor cores
    gemm_tf32<<<gemm_grid, gemm_block>>>(x, Wq, bq, nullptr, q, Hdim, Hdim, 1);
    gemm_tf32<<<gemm_grid, gemm_block>>>(x, Wk, bk, nullptr, k, Hdim, Hdim, 1);
    gemm_tf32<<<gemm_grid, gemm_block>>>(x, Wv, bv, nullptr, v, Hdim, Hdim, 0);

    // zero kv state (graph replays must be deterministic)
    const int kvn = Bsz * NHEAD * HDm * HDm;
    const int ksn = Bsz * NHEAD * HDm;
    zero_kernel<<<(kvn + 255) / 256, 256>>>(kv, kvn);
    zero_kernel<<<(ksn + 255) / 256, 256>>>(ksum, ksn);

    // kv state + ksum
    kv_accum<<<dim3(Bsz * NHEAD, 8), 256>>>(k, v, kv, ksum);

    // ctx (reuses g_k — k is dead after kv_accum)
    ctx_kernel<<<dim3(Bsz * NHEAD, Sseq / 128), 256>>>(q, kv, ksum, k);

    // output projection + bias + residual (hs reuses g_q — q is dead now)
    gemm_tf32<<<gemm_grid, gemm_block>>>(k, Wd, bd, x, q, Hdim, Hdim, 0);

    // LayerNorm
    ln_kernel<<<BSROWS, 256>>>(q, gamma, beta, out);
}

// round 4
// speedup vs baseline: 4.0237x; 1.8888x over previous
#include <cuda_runtime.h>
#include <cuda_bf16.h>
#include <cstdint>
#include <math.h>

#define Bsz 8
#define Sseq 4096
#define Hdim 1024
#define NHEAD 16
#define HDm 64
#define BSROWS (Bsz * Sseq)          // 32768
#define EPS_ATTN 1e-6f
#define EPS_LN 1e-12f

// ---------------- scratch (device globals; no allocation allowed) -----------
__device__ float g_q[(size_t)BSROWS * Hdim];            // q, later reused as hs
__device__ float g_k[(size_t)BSROWS * Hdim];            // k
__device__ float g_v[(size_t)BSROWS * Hdim];            // v
__device__ float g_kv[Bsz * NHEAD * HDm * HDm];         // kv state [bh][m][d]
__device__ float g_ksum[Bsz * NHEAD * HDm];             // sum_s k  [bh][d]
__device__ __nv_bfloat16 g_xb[(size_t)BSROWS * Hdim];   // x in bf16
__device__ __nv_bfloat16 g_cb[(size_t)BSROWS * Hdim];   // ctx in bf16
__device__ __nv_bfloat16 g_wq[Hdim * Hdim];
__device__ __nv_bfloat16 g_wk[Hdim * Hdim];
__device__ __nv_bfloat16 g_wv[Hdim * Hdim];
__device__ __nv_bfloat16 g_wd[Hdim * Hdim];

// ---------------- PTX helpers -------------------------------------------------
__device__ __forceinline__ uint32_t smem_u32(const void* p) {
    uint32_t a;
    asm("{ .reg .u64 t; cvta.to.shared.u64 t, %1; cvt.u32.u64 %0, t; }" : "=r"(a) : "l"(p));
    return a;
}

__device__ __forceinline__ void ldm_x4(uint32_t& d0, uint32_t& d1, uint32_t& d2,
                                       uint32_t& d3, uint32_t addr) {
    asm volatile("ldmatrix.sync.aligned.m8n8.x4.shared.b16 {%0,%1,%2,%3}, [%4];"
                 : "=r"(d0), "=r"(d1), "=r"(d2), "=r"(d3) : "r"(addr));
}

__device__ __forceinline__ void mma_bf16(float* c, const uint32_t* a, const uint32_t* b) {
    asm volatile(
        "mma.sync.aligned.m16n8k16.row.col.f32.bf16.bf16.f32 "
        "{%0,%1,%2,%3}, {%4,%5,%6,%7}, {%8,%9}, {%0,%1,%2,%3};"
        : "+f"(c[0]), "+f"(c[1]), "+f"(c[2]), "+f"(c[3])
        : "r"(a[0]), "r"(a[1]), "r"(a[2]), "r"(a[3]), "r"(b[0]), "r"(b[1]));
}

// ---------------- BF16 tensor-core GEMM: C = A[M,K]bf16 @ W[N,K]^T bf16 ------
// 128x128 tile, BK=32, 8 warps (2x4), warp tile 64x32 via m16n8k16 + ldmatrix.
// Smem rows: 32 bf16 data + 8 pad = 40 bf16 = 80B -> conflict-free ldmatrix.
#define BKb 32
#define LDB 40

__global__ __launch_bounds__(256)
void gemm_bf16(const __nv_bfloat16* __restrict__ A, const __nv_bfloat16* __restrict__ W,
               const float* __restrict__ bias, const float* __restrict__ resid,
               float* __restrict__ C, int K, int N, int act)
{
    __shared__ __nv_bfloat16 As[2][128 * LDB];
    __shared__ __nv_bfloat16 Ws[2][128 * LDB];

    const int tid  = threadIdx.x;
    const int lane = tid & 31;
    const int wid  = tid >> 5;
    const int wm   = wid & 1;           // warp row (2)
    const int wn   = wid >> 1;          // warp col (4)
    const int row0 = blockIdx.y * 128;
    const int col0 = blockIdx.x * 128;

    // global->smem mapping: thread covers rows r0 and r0+64, 8-bf16 seg ks
    const int r0 = tid >> 2;            // 0..63
    const int ks = (tid & 3) * 8;       // bf16 col offset 0,8,16,24

    const __nv_bfloat16* Ap0 = A + (size_t)(row0 + r0) * K + ks;
    const __nv_bfloat16* Ap1 = Ap0 + (size_t)64 * K;
    const __nv_bfloat16* Wp0 = W + (size_t)(col0 + r0) * K + ks;
    const __nv_bfloat16* Wp1 = Wp0 + (size_t)64 * K;

    const uint32_t asb = smem_u32(&As[0][0]);
    const uint32_t wsb = smem_u32(&Ws[0][0]);
    const uint32_t bufstride = 128 * LDB * 2;   // bytes per buffer

    const uint32_t st_off = (uint32_t)(r0 * LDB + ks) * 2;

    // ldmatrix lane-invariant offsets (bytes)
    const uint32_t a_lane = ((uint32_t)((wm * 64 + (lane & 15)) * LDB + (lane >> 4) * 8)) * 2;
    const uint32_t b_lane = ((uint32_t)((wn * 32 + ((lane >> 4) << 3) + (lane & 7)) * LDB
                                        + ((lane >> 3) & 1) * 8)) * 2;

    float acc[4][4][4] = {};

    const int nt = K / BKb;             // 32

    // preload tile 0
    uint4 ra0 = *(const uint4*)Ap0;
    uint4 ra1 = *(const uint4*)Ap1;
    uint4 rw0 = *(const uint4*)Wp0;
    uint4 rw1 = *(const uint4*)Wp1;
    *(uint4*)((char*)As[0] + st_off) = ra0;
    *(uint4*)((char*)As[0] + st_off + 64 * LDB * 2) = ra1;
    *(uint4*)((char*)Ws[0] + st_off) = rw0;
    *(uint4*)((char*)Ws[0] + st_off + 64 * LDB * 2) = rw1;
    __syncthreads();

    for (int kt = 0; kt < nt; kt++) {
        const int buf = kt & 1;
        if (kt + 1 < nt) {
            const int g = (kt + 1) * BKb;
            ra0 = *(const uint4*)(Ap0 + g);
            ra1 = *(const uint4*)(Ap1 + g);
            rw0 = *(const uint4*)(Wp0 + g);
            rw1 = *(const uint4*)(Wp1 + g);
        }

        const uint32_t ab = asb + buf * bufstride + a_lane;
        const uint32_t bb = wsb + buf * bufstride + b_lane;

        #pragma unroll
        for (int kk = 0; kk < BKb; kk += 16) {
            uint32_t af[4][4], bf[4][2];
            #pragma unroll
            for (int mf = 0; mf < 4; mf++)
                ldm_x4(af[mf][0], af[mf][1], af[mf][2], af[mf][3],
                       ab + (uint32_t)(mf * 16 * LDB + kk) * 2);
            #pragma unroll
            for (int np = 0; np < 2; np++)
                ldm_x4(bf[np * 2][0], bf[np * 2][1], bf[np * 2 + 1][0], bf[np * 2 + 1][1],
                       bb + (uint32_t)(np * 16 * LDB + kk) * 2);
            #pragma unroll
            for (int mf = 0; mf < 4; mf++)
                #pragma unroll
                for (int nf = 0; nf < 4; nf++)
                    mma_bf16(acc[mf][nf], af[mf], bf[nf]);
        }

        if (kt + 1 < nt) {
            const int nb = buf ^ 1;
            *(uint4*)((char*)As[nb] + st_off) = ra0;
            *(uint4*)((char*)As[nb] + st_off + 64 * LDB * 2) = ra1;
            *(uint4*)((char*)Ws[nb] + st_off) = rw0;
            *(uint4*)((char*)Ws[nb] + st_off + 64 * LDB * 2) = rw1;
            __syncthreads();
        }
    }

    // epilogue: bias (+resid) (+elu+1)
    #pragma unroll
    for (int mf = 0; mf < 4; mf++) {
        #pragma unroll
        for (int nf = 0; nf < 4; nf++) {
            const int r   = row0 + wm * 64 + mf * 16 + (lane >> 2);
            const int cgl = col0 + wn * 32 + nf * 8 + 2 * (lane & 3);
            const float b0 = bias[cgl], b1 = bias[cgl + 1];
            #pragma unroll
            for (int half = 0; half < 2; half++) {
                const int rr = r + half * 8;
                float v0 = acc[mf][nf][half * 2 + 0] + b0;
                float v1 = acc[mf][nf][half * 2 + 1] + b1;
                if (resid) {
                    const float* rp = resid + (size_t)rr * N + cgl;
                    v0 += rp[0];
                    v1 += rp[1];
                }
                if (act) {
                    v0 = (v0 > 0.f) ? (v0 + 1.f) : expf(v0);
                    v1 = (v1 > 0.f) ? (v1 + 1.f) : expf(v1);
                }
                *(float2*)(C + (size_t)rr * N + cgl) = make_float2(v0, v1);
            }
        }
    }
}

// ---------------- f32 -> bf16 conversion -------------------------------------
__global__ void __launch_bounds__(256)
conv_bf16(const float* __restrict__ in, __nv_bfloat16* __restrict__ out, int n4)
{
    const int i = blockIdx.x * blockDim.x + threadIdx.x;
    if (i < n4) {
        float4 v = ((const float4*)in)[i];
        __nv_bfloat162 lo = __floats2bfloat162_rn(v.x, v.y);
        __nv_bfloat162 hi = __floats2bfloat162_rn(v.z, v.w);
        uint2 u;
        u.x = *reinterpret_cast<uint32_t*>(&lo);
        u.y = *reinterpret_cast<uint32_t*>(&hi);
        ((uint2*)out)[i] = u;
    }
}

// ---------------- kv state + ksum:  kv[bh][m][d] = sum_s v[s][m] * k[s][d]
__global__ __launch_bounds__(256)
void kv_accum(const float* __restrict__ k, const float* __restrict__ v,
              float* __restrict__ kv, float* __restrict__ ksum)
{
    const int bh = blockIdx.x;
    const int b  = bh / NHEAD, h = bh % NHEAD;
    const int s0 = blockIdx.y * (Sseq / 8);

    __shared__ float ks[4][HDm];
    __shared__ float vs[4][HDm];

    const int tid = threadIdx.x;
    const int tx = tid & 15, ty = tid >> 4;
    const int d0 = tx * 4, m0 = ty * 4;
    const int tt = tid >> 6;
    const int cc = tid & 63;

    float acc[4][4];
    #pragma unroll
    for (int m = 0; m < 4; m++)
        #pragma unroll
        for (int d = 0; d < 4; d++) acc[m][d] = 0.f;
    float kloc = 0.f;

    for (int s = s0; s < s0 + Sseq / 8; s += 4) {
        __syncthreads();
        const size_t base = ((size_t)(b * Sseq + s + tt)) * Hdim + h * HDm + cc;
        ks[tt][cc] = k[base];
        vs[tt][cc] = v[base];
        __syncthreads();

        #pragma unroll
        for (int t = 0; t < 4; t++) {
            float kk4[4] = {ks[t][d0], ks[t][d0 + 1], ks[t][d0 + 2], ks[t][d0 + 3]};
            float vv4[4] = {vs[t][m0], vs[t][m0 + 1], vs[t][m0 + 2], vs[t][m0 + 3]};
            #pragma unroll
            for (int m = 0; m < 4; m++)
                #pragma unroll
                for (int d = 0; d < 4; d++)
                    acc[m][d] = fmaf(vv4[m], kk4[d], acc[m][d]);
        }
        if (tid < HDm)
            kloc += ks[0][tid] + ks[1][tid] + ks[2][tid] + ks[3][tid];
    }

    float* kvp = kv + (size_t)bh * HDm * HDm;
    #pragma unroll
    for (int m = 0; m < 4; m++)
        #pragma unroll
        for (int d = 0; d < 4; d++)
            atomicAdd(&kvp[(m0 + m) * HDm + (d0 + d)], acc[m][d]);
    if (tid < HDm) atomicAdd(&ksum[bh * HDm + tid], kloc);
}

// ---------------- ctx[s][m] = (q[s].kv[m,:]) / (q[s].(ksum+eps)) -> bf16
__global__ __launch_bounds__(256)
void ctx_kernel(const float* __restrict__ q, const float* __restrict__ kv,
                const float* __restrict__ ksum, __nv_bfloat16* __restrict__ ctx)
{
    const int bh = blockIdx.x;
    const int b = bh / NHEAD, h = bh % NHEAD;
    const int s0 = blockIdx.y * 128;

    __shared__ float kvT[HDm][HDm];
    __shared__ float kse[HDm];
    __shared__ float qsh[4][HDm];

    const int tid = threadIdx.x;
    const float* kvp = kv + (size_t)bh * HDm * HDm;
    for (int i = tid; i < HDm * HDm; i += 256)
        kvT[i & 63][i >> 6] = kvp[i];
    if (tid < HDm) kse[tid] = ksum[bh * HDm + tid] + EPS_ATTN;
    __syncthreads();

    const int ty = tid >> 6;
    const int m  = tid & 63;

    for (int g = 0; g < 32; g++) {
        const int s = s0 + g * 4 + ty;
        const size_t base = ((size_t)(b * Sseq + s)) * Hdim + h * HDm;
        qsh[ty][m] = q[base + m];
        __syncthreads();

        float dot = 0.f, acc = 0.f;
        #pragma unroll 8
        for (int d = 0; d < HDm; d++) {
            const float qd = qsh[ty][d];
            dot = fmaf(qd, kse[d], dot);
            acc = fmaf(qd, kvT[d][m], acc);
        }
        ctx[base + m] = __float2bfloat16(acc / dot);
        __syncthreads();
    }
}

// ---------------- LayerNorm over rows of 1024
__global__ __launch_bounds__(256)
void ln_kernel(const float* __restrict__ hs, const float* __restrict__ gamma,
               const float* __restrict__ beta, float* __restrict__ out)
{
    const int row = blockIdx.x;
    const int tid = threadIdx.x;
    const float4 v = ((const float4*)(hs + (size_t)row * Hdim))[tid];

    float s  = v.x + v.y + v.z + v.w;
    float sq = v.x * v.x + v.y * v.y + v.z * v.z + v.w * v.w;
    #pragma unroll
    for (int o = 16; o > 0; o >>= 1) {
        s  += __shfl_xor_sync(0xFFFFFFFFu, s, o);
        sq += __shfl_xor_sync(0xFFFFFFFFu, sq, o);
    }
    __shared__ float rs[8], rq[8];
    const int wid = tid >> 5, lane = tid & 31;
    if (lane == 0) { rs[wid] = s; rq[wid] = sq; }
    __syncthreads();
    float sum = 0.f, sumq = 0.f;
    #pragma unroll
    for (int i = 0; i < 8; i++) { sum += rs[i]; sumq += rq[i]; }

    const float mu   = sum * (1.f / Hdim);
    const float var  = sumq * (1.f / Hdim) - mu * mu;
    const float rstd = rsqrtf(var + EPS_LN);

    const float4 g4 = ((const float4*)gamma)[tid];
    const float4 b4 = ((const float4*)beta)[tid];
    float4 o;
    o.x = (v.x - mu) * rstd * g4.x + b4.x;
    o.y = (v.y - mu) * rstd * g4.y + b4.y;
    o.z = (v.z - mu) * rstd * g4.z + b4.z;
    o.w = (v.w - mu) * rstd * g4.w + b4.w;
    ((float4*)(out + (size_t)row * Hdim))[tid] = o;
}

__global__ void zero_kernel(float* p, int n)
{
    const int i = blockIdx.x * blockDim.x + threadIdx.x;
    if (i < n) p[i] = 0.f;
}

// ---------------- launch ----------------------------------------------------
extern "C" void kernel_launch(void* const* d_in, const int* in_sizes, int n_in,
                              void* d_out, int out_size)
{
    const float* x     = (const float*)d_in[0];
    const float* Wq    = (const float*)d_in[2];
    const float* bq    = (const float*)d_in[3];
    const float* Wk    = (const float*)d_in[4];
    const float* bk    = (const float*)d_in[5];
    const float* Wv    = (const float*)d_in[6];
    const float* bv    = (const float*)d_in[7];
    const float* Wd    = (const float*)d_in[8];
    const float* bd    = (const float*)d_in[9];
    const float* gamma = (const float*)d_in[10];
    const float* beta  = (const float*)d_in[11];
    float* out = (float*)d_out;

    float *q, *k, *v, *kv, *ksum;
    __nv_bfloat16 *xb, *cb, *wqb, *wkb, *wvb, *wdb;
    cudaGetSymbolAddress((void**)&q,    g_q);
    cudaGetSymbolAddress((void**)&k,    g_k);
    cudaGetSymbolAddress((void**)&v,    g_v);
    cudaGetSymbolAddress((void**)&kv,   g_kv);
    cudaGetSymbolAddress((void**)&ksum, g_ksum);
    cudaGetSymbolAddress((void**)&xb,   g_xb);
    cudaGetSymbolAddress((void**)&cb,   g_cb);
    cudaGetSymbolAddress((void**)&wqb,  g_wq);
    cudaGetSymbolAddress((void**)&wkb,  g_wk);
    cudaGetSymbolAddress((void**)&wvb,  g_wv);
    cudaGetSymbolAddress((void**)&wdb,  g_wd);

    // convert inputs to bf16
    const int xn4 = (int)((size_t)BSROWS * Hdim / 4);
    const int wn4 = Hdim * Hdim / 4;
    conv_bf16<<<xn4 / 256, 256>>>(x,  xb,  xn4);
    conv_bf16<<<wn4 / 256, 256>>>(Wq, wqb, wn4);
    conv_bf16<<<wn4 / 256, 256>>>(Wk, wkb, wn4);
    conv_bf16<<<wn4 / 256, 256>>>(Wv, wvb, wn4);
    conv_bf16<<<wn4 / 256, 256>>>(Wd, wdb, wn4);

    const dim3 ggrid(Hdim / 128, BSROWS / 128);   // (8, 256)

    // QKV projections (+ elu+1 on q,k) — bf16 m16n8k16 tensor cores
    gemm_bf16<<<ggrid, 256>>>(xb, wqb, bq, nullptr, q, Hdim, Hdim, 1);
    gemm_bf16<<<ggrid, 256>>>(xb, wkb, bk, nullptr, k, Hdim, Hdim, 1);
    gemm_bf16<<<ggrid, 256>>>(xb, wvb, bv, nullptr, v, Hdim, Hdim, 0);

    // zero kv state (graph replays must be deterministic)
    const int kvn = Bsz * NHEAD * HDm * HDm;
    const int ksn = Bsz * NHEAD * HDm;
    zero_kernel<<<(kvn + 255) / 256, 256>>>(kv, kvn);
    zero_kernel<<<(ksn + 255) / 256, 256>>>(ksum, ksn);

    // kv state + ksum
    kv_accum<<<dim3(Bsz * NHEAD, 8), 256>>>(k, v, kv, ksum);

    // ctx -> bf16
    ctx_kernel<<<dim3(Bsz * NHEAD, Sseq / 128), 256>>>(q, kv, ksum, cb);

    // output projection + bias + residual (hs reuses g_q)
    gemm_bf16<<<ggrid, 256>>>(cb, wdb, bd, x, q, Hdim, Hdim, 0);

    // LayerNorm
    ln_kernel<<<BSROWS, 256>>>(q, gamma, beta, out);
}

// round 5
// speedup vs baseline: 4.1898x; 1.0413x over previous
#include <cuda_runtime.h>
#include <cuda_bf16.h>
#include <cstdint>
#include <math.h>

#define Bsz 8
#define Sseq 4096
#define Hdim 1024
#define NHEAD 16
#define HDm 64
#define BSROWS (Bsz * Sseq)          // 32768
#define EPS_ATTN 1e-6f
#define EPS_LN 1e-12f

// ---------------- scratch (device globals; no allocation allowed) -----------
__device__ float g_hs[(size_t)BSROWS * Hdim];            // hs (f32)
__device__ __nv_bfloat16 g_qb[(size_t)BSROWS * Hdim];    // q bf16
__device__ __nv_bfloat16 g_kb[(size_t)BSROWS * Hdim];    // k bf16
__device__ __nv_bfloat16 g_vb[(size_t)BSROWS * Hdim];    // v bf16
__device__ float g_kv[Bsz * NHEAD * HDm * HDm];          // kv state [bh][m][d]
__device__ float g_ksum[Bsz * NHEAD * HDm];              // sum_s k  [bh][d]
__device__ __nv_bfloat16 g_xb[(size_t)BSROWS * Hdim];    // x in bf16
__device__ __nv_bfloat16 g_cb[(size_t)BSROWS * Hdim];    // ctx in bf16
__device__ __nv_bfloat16 g_wq[Hdim * Hdim];
__device__ __nv_bfloat16 g_wk[Hdim * Hdim];
__device__ __nv_bfloat16 g_wv[Hdim * Hdim];
__device__ __nv_bfloat16 g_wd[Hdim * Hdim];

// ---------------- PTX helpers -------------------------------------------------
__device__ __forceinline__ uint32_t smem_u32(const void* p) {
    uint32_t a;
    asm("{ .reg .u64 t; cvta.to.shared.u64 t, %1; cvt.u32.u64 %0, t; }" : "=r"(a) : "l"(p));
    return a;
}

__device__ __forceinline__ void ldm_x4(uint32_t& d0, uint32_t& d1, uint32_t& d2,
                                       uint32_t& d3, uint32_t addr) {
    asm volatile("ldmatrix.sync.aligned.m8n8.x4.shared.b16 {%0,%1,%2,%3}, [%4];"
                 : "=r"(d0), "=r"(d1), "=r"(d2), "=r"(d3) : "r"(addr));
}

__device__ __forceinline__ void mma_bf16(float* c, const uint32_t* a, const uint32_t* b) {
    asm volatile(
        "mma.sync.aligned.m16n8k16.row.col.f32.bf16.bf16.f32 "
        "{%0,%1,%2,%3}, {%4,%5,%6,%7}, {%8,%9}, {%0,%1,%2,%3};"
        : "+f"(c[0]), "+f"(c[1]), "+f"(c[2]), "+f"(c[3])
        : "r"(a[0]), "r"(a[1]), "r"(a[2]), "r"(a[3]), "r"(b[0]), "r"(b[1]));
}

__device__ __forceinline__ void cp16(uint32_t dst, const void* src) {
    asm volatile("cp.async.cg.shared.global [%0], [%1], 16;" :: "r"(dst), "l"(src));
}
#define CP_COMMIT() asm volatile("cp.async.commit_group;" ::: "memory")
#define CP_WAIT1()  asm volatile("cp.async.wait_group 1;" ::: "memory")
#define CP_WAIT0()  asm volatile("cp.async.wait_group 0;" ::: "memory")

// ---------------- BF16 tensor-core GEMM: C = A[M,K]bf16 @ W[N,K]^T bf16 ------
// 128x128 tile, BK=32, 3-stage cp.async pipeline, 8 warps (2x4),
// warp tile 64x32 via m16n8k16 + ldmatrix. Rows padded to 40 bf16 (80B).
#define BKb 32
#define LDB 40
#define STG 3
#define TILEB (128 * LDB * 2)        // 10240 B per operand tile
#define STGB  (2 * TILEB)            // 20480 B per stage
#define GSM_TOT (STG * STGB)         // 61440 B

__global__ __launch_bounds__(256, 2)
void gemm_bf16(const __nv_bfloat16* __restrict__ A, const __nv_bfloat16* __restrict__ W,
               const float* __restrict__ bias, const float* __restrict__ resid,
               float* __restrict__ Cf, __nv_bfloat16* __restrict__ Cb,
               int K, int N, int act)
{
    extern __shared__ char smem[];
    const uint32_t smb = smem_u32(smem);

    const int tid  = threadIdx.x;
    const int lane = tid & 31;
    const int wid  = tid >> 5;
    const int wm   = wid & 1;           // warp row (2)
    const int wn   = wid >> 1;          // warp col (4)
    const int row0 = blockIdx.y * 128;
    const int col0 = blockIdx.x * 128;

    // global->smem mapping: thread covers rows r0 and r0+64, 8-bf16 seg ks
    const int r0 = tid >> 2;            // 0..63
    const int ks = (tid & 3) * 8;       // bf16 col offset 0,8,16,24

    const __nv_bfloat16* Ap0 = A + (size_t)(row0 + r0) * K + ks;
    const __nv_bfloat16* Ap1 = Ap0 + (size_t)64 * K;
    const __nv_bfloat16* Wp0 = W + (size_t)(col0 + r0) * K + ks;
    const __nv_bfloat16* Wp1 = Wp0 + (size_t)64 * K;

    const uint32_t st_off = (uint32_t)(r0 * LDB + ks) * 2;

    // ldmatrix lane-invariant offsets (bytes)
    const uint32_t a_lane = ((uint32_t)((wm * 64 + (lane & 15)) * LDB + (lane >> 4) * 8)) * 2;
    const uint32_t b_lane = ((uint32_t)((wn * 32 + ((lane >> 4) << 3) + (lane & 7)) * LDB
                                        + ((lane >> 3) & 1) * 8)) * 2;

    float acc[4][4][4] = {};
    const int nt = K / BKb;             // 32

    // prologue: stages 0,1
    #pragma unroll
    for (int s = 0; s < 2; s++) {
        const int g = s * BKb;
        const uint32_t sb = smb + s * STGB;
        cp16(sb + st_off, Ap0 + g);
        cp16(sb + st_off + 64 * LDB * 2, Ap1 + g);
        cp16(sb + TILEB + st_off, Wp0 + g);
        cp16(sb + TILEB + st_off + 64 * LDB * 2, Wp1 + g);
        CP_COMMIT();
    }

    int stage = 0;
    for (int kt = 0; kt < nt; kt++) {
        if (kt == nt - 1) CP_WAIT0(); else CP_WAIT1();
        __syncthreads();

        if (kt + 2 < nt) {
            const int g = (kt + 2) * BKb;
            const int s2 = (stage + 2 >= STG) ? (stage + 2 - STG) : (stage + 2);
            const uint32_t sb = smb + s2 * STGB;
            cp16(sb + st_off, Ap0 + g);
            cp16(sb + st_off + 64 * LDB * 2, Ap1 + g);
            cp16(sb + TILEB + st_off, Wp0 + g);
            cp16(sb + TILEB + st_off + 64 * LDB * 2, Wp1 + g);
            CP_COMMIT();
        }

        const uint32_t ab = smb + stage * STGB + a_lane;
        const uint32_t bb = smb + stage * STGB + TILEB + b_lane;

        #pragma unroll
        for (int kk = 0; kk < BKb; kk += 16) {
            uint32_t af[4][4], bf[4][2];
            #pragma unroll
            for (int mf = 0; mf < 4; mf++)
                ldm_x4(af[mf][0], af[mf][1], af[mf][2], af[mf][3],
                       ab + (uint32_t)(mf * 16 * LDB + kk) * 2);
            #pragma unroll
            for (int np = 0; np < 2; np++)
                ldm_x4(bf[np * 2][0], bf[np * 2][1], bf[np * 2 + 1][0], bf[np * 2 + 1][1],
                       bb + (uint32_t)(np * 16 * LDB + kk) * 2);
            #pragma unroll
            for (int mf = 0; mf < 4; mf++)
                #pragma unroll
                for (int nf = 0; nf < 4; nf++)
                    mma_bf16(acc[mf][nf], af[mf], bf[nf]);
        }

        stage = (stage + 1 == STG) ? 0 : (stage + 1);
    }

    // epilogue: bias (+resid) (+elu+1); output f32 or bf16
    #pragma unroll
    for (int mf = 0; mf < 4; mf++) {
        #pragma unroll
        for (int nf = 0; nf < 4; nf++) {
            const int r   = row0 + wm * 64 + mf * 16 + (lane >> 2);
            const int cgl = col0 + wn * 32 + nf * 8 + 2 * (lane & 3);
            const float b0 = bias[cgl], b1 = bias[cgl + 1];
            #pragma unroll
            for (int half = 0; half < 2; half++) {
                const int rr = r + half * 8;
                float v0 = acc[mf][nf][half * 2 + 0] + b0;
                float v1 = acc[mf][nf][half * 2 + 1] + b1;
                if (resid) {
                    const float* rp = resid + (size_t)rr * N + cgl;
                    v0 += rp[0];
                    v1 += rp[1];
                }
                if (act) {
                    v0 = (v0 > 0.f) ? (v0 + 1.f) : expf(v0);
                    v1 = (v1 > 0.f) ? (v1 + 1.f) : expf(v1);
                }
                if (Cb) {
                    *(__nv_bfloat162*)(Cb + (size_t)rr * N + cgl) =
                        __floats2bfloat162_rn(v0, v1);
                } else {
                    *(float2*)(Cf + (size_t)rr * N + cgl) = make_float2(v0, v1);
                }
            }
        }
    }
}

// ---------------- f32 -> bf16 conversion -------------------------------------
__global__ void __launch_bounds__(256)
conv_bf16(const float* __restrict__ in, __nv_bfloat16* __restrict__ out, int n4)
{
    const int i = blockIdx.x * blockDim.x + threadIdx.x;
    if (i < n4) {
        float4 v = ((const float4*)in)[i];
        __nv_bfloat162 lo = __floats2bfloat162_rn(v.x, v.y);
        __nv_bfloat162 hi = __floats2bfloat162_rn(v.z, v.w);
        uint2 u;
        u.x = *reinterpret_cast<uint32_t*>(&lo);
        u.y = *reinterpret_cast<uint32_t*>(&hi);
        ((uint2*)out)[i] = u;
    }
}

// ---------------- kv state + ksum:  kv[bh][m][d] = sum_s v[s][m] * k[s][d]
__global__ __launch_bounds__(256)
void kv_accum(const __nv_bfloat16* __restrict__ k, const __nv_bfloat16* __restrict__ v,
              float* __restrict__ kv, float* __restrict__ ksum)
{
    const int bh = blockIdx.x;
    const int b  = bh / NHEAD, h = bh % NHEAD;
    const int s0 = blockIdx.y * (Sseq / 8);

    __shared__ float ks[4][HDm];
    __shared__ float vs[4][HDm];

    const int tid = threadIdx.x;
    const int tx = tid & 15, ty = tid >> 4;
    const int d0 = tx * 4, m0 = ty * 4;
    const int tt = tid >> 6;
    const int cc = tid & 63;

    float acc[4][4];
    #pragma unroll
    for (int m = 0; m < 4; m++)
        #pragma unroll
        for (int d = 0; d < 4; d++) acc[m][d] = 0.f;
    float kloc = 0.f;

    for (int s = s0; s < s0 + Sseq / 8; s += 4) {
        __syncthreads();
        const size_t base = ((size_t)(b * Sseq + s + tt)) * Hdim + h * HDm + cc;
        ks[tt][cc] = __bfloat162float(k[base]);
        vs[tt][cc] = __bfloat162float(v[base]);
        __syncthreads();

        #pragma unroll
        for (int t = 0; t < 4; t++) {
            float kk4[4] = {ks[t][d0], ks[t][d0 + 1], ks[t][d0 + 2], ks[t][d0 + 3]};
            float vv4[4] = {vs[t][m0], vs[t][m0 + 1], vs[t][m0 + 2], vs[t][m0 + 3]};
            #pragma unroll
            for (int m = 0; m < 4; m++)
                #pragma unroll
                for (int d = 0; d < 4; d++)
                    acc[m][d] = fmaf(vv4[m], kk4[d], acc[m][d]);
        }
        if (tid < HDm)
            kloc += ks[0][tid] + ks[1][tid] + ks[2][tid] + ks[3][tid];
    }

    float* kvp = kv + (size_t)bh * HDm * HDm;
    #pragma unroll
    for (int m = 0; m < 4; m++)
        #pragma unroll
        for (int d = 0; d < 4; d++)
            atomicAdd(&kvp[(m0 + m) * HDm + (d0 + d)], acc[m][d]);
    if (tid < HDm) atomicAdd(&ksum[bh * HDm + tid], kloc);
}

// ---------------- ctx[s][m] = (q[s].kv[m,:]) / (q[s].(ksum+eps)) -> bf16
__global__ __launch_bounds__(256)
void ctx_kernel(const __nv_bfloat16* __restrict__ q, const float* __restrict__ kv,
                const float* __restrict__ ksum, __nv_bfloat16* __restrict__ ctx)
{
    const int bh = blockIdx.x;
    const int b = bh / NHEAD, h = bh % NHEAD;
    const int s0 = blockIdx.y * 128;

    __shared__ float kvT[HDm][HDm];
    __shared__ float kse[HDm];
    __shared__ float qsh[4][HDm];

    const int tid = threadIdx.x;
    const float* kvp = kv + (size_t)bh * HDm * HDm;
    for (int i = tid; i < HDm * HDm; i += 256)
        kvT[i & 63][i >> 6] = kvp[i];
    if (tid < HDm) kse[tid] = ksum[bh * HDm + tid] + EPS_ATTN;
    __syncthreads();

    const int ty = tid >> 6;
    const int m  = tid & 63;

    for (int g = 0; g < 32; g++) {
        const int s = s0 + g * 4 + ty;
        const size_t base = ((size_t)(b * Sseq + s)) * Hdim + h * HDm;
        qsh[ty][m] = __bfloat162float(q[base + m]);
        __syncthreads();

        float dot = 0.f, acc = 0.f;
        #pragma unroll 8
        for (int d = 0; d < HDm; d++) {
            const float qd = qsh[ty][d];
            dot = fmaf(qd, kse[d], dot);
            acc = fmaf(qd, kvT[d][m], acc);
        }
        ctx[base + m] = __float2bfloat16(acc / dot);
        __syncthreads();
    }
}

// ---------------- LayerNorm over rows of 1024
__global__ __launch_bounds__(256)
void ln_kernel(const float* __restrict__ hs, const float* __restrict__ gamma,
               const float* __restrict__ beta, float* __restrict__ out)
{
    const int row = blockIdx.x;
    const int tid = threadIdx.x;
    const float4 v = ((const float4*)(hs + (size_t)row * Hdim))[tid];

    float s  = v.x + v.y + v.z + v.w;
    float sq = v.x * v.x + v.y * v.y + v.z * v.z + v.w * v.w;
    #pragma unroll
    for (int o = 16; o > 0; o >>= 1) {
        s  += __shfl_xor_sync(0xFFFFFFFFu, s, o);
        sq += __shfl_xor_sync(0xFFFFFFFFu, sq, o);
    }
    __shared__ float rs[8], rq[8];
    const int wid = tid >> 5, lane = tid & 31;
    if (lane == 0) { rs[wid] = s; rq[wid] = sq; }
    __syncthreads();
    float sum = 0.f, sumq = 0.f;
    #pragma unroll
    for (int i = 0; i < 8; i++) { sum += rs[i]; sumq += rq[i]; }

    const float mu   = sum * (1.f / Hdim);
    const float var  = sumq * (1.f / Hdim) - mu * mu;
    const float rstd = rsqrtf(var + EPS_LN);

    const float4 g4 = ((const float4*)gamma)[tid];
    const float4 b4 = ((const float4*)beta)[tid];
    float4 o;
    o.x = (v.x - mu) * rstd * g4.x + b4.x;
    o.y = (v.y - mu) * rstd * g4.y + b4.y;
    o.z = (v.z - mu) * rstd * g4.z + b4.z;
    o.w = (v.w - mu) * rstd * g4.w + b4.w;
    ((float4*)(out + (size_t)row * Hdim))[tid] = o;
}

__global__ void zero_kernel(float* p, int n)
{
    const int i = blockIdx.x * blockDim.x + threadIdx.x;
    if (i < n) p[i] = 0.f;
}

// ---------------- launch ----------------------------------------------------
extern "C" void kernel_launch(void* const* d_in, const int* in_sizes, int n_in,
                              void* d_out, int out_size)
{
    const float* x     = (const float*)d_in[0];
    const float* Wq    = (const float*)d_in[2];
    const float* bq    = (const float*)d_in[3];
    const float* Wk    = (const float*)d_in[4];
    const float* bk    = (const float*)d_in[5];
    const float* Wv    = (const float*)d_in[6];
    const float* bv    = (const float*)d_in[7];
    const float* Wd    = (const float*)d_in[8];
    const float* bd    = (const float*)d_in[9];
    const float* gamma = (const float*)d_in[10];
    const float* beta  = (const float*)d_in[11];
    float* out = (float*)d_out;

    float *hs, *kv, *ksum;
    __nv_bfloat16 *qb, *kb, *vb, *xb, *cb, *wqb, *wkb, *wvb, *wdb;
    cudaGetSymbolAddress((void**)&hs,   g_hs);
    cudaGetSymbolAddress((void**)&qb,   g_qb);
    cudaGetSymbolAddress((void**)&kb,   g_kb);
    cudaGetSymbolAddress((void**)&vb,   g_vb);
    cudaGetSymbolAddress((void**)&kv,   g_kv);
    cudaGetSymbolAddress((void**)&ksum, g_ksum);
    cudaGetSymbolAddress((void**)&xb,   g_xb);
    cudaGetSymbolAddress((void**)&cb,   g_cb);
    cudaGetSymbolAddress((void**)&wqb,  g_wq);
    cudaGetSymbolAddress((void**)&wkb,  g_wk);
    cudaGetSymbolAddress((void**)&wvb,  g_wv);
    cudaGetSymbolAddress((void**)&wdb,  g_wd);

    cudaFuncSetAttribute(gemm_bf16, cudaFuncAttributeMaxDynamicSharedMemorySize, GSM_TOT);

    // convert inputs to bf16
    const int xn4 = (int)((size_t)BSROWS * Hdim / 4);
    const int wn4 = Hdim * Hdim / 4;
    conv_bf16<<<xn4 / 256, 256>>>(x,  xb,  xn4);
    conv_bf16<<<wn4 / 256, 256>>>(Wq, wqb, wn4);
    conv_bf16<<<wn4 / 256, 256>>>(Wk, wkb, wn4);
    conv_bf16<<<wn4 / 256, 256>>>(Wv, wvb, wn4);
    conv_bf16<<<wn4 / 256, 256>>>(Wd, wdb, wn4);

    const dim3 ggrid(Hdim / 128, BSROWS / 128);   // (8, 256)

    // QKV projections (+ elu+1 on q,k) — bf16 outputs
    gemm_bf16<<<ggrid, 256, GSM_TOT>>>(xb, wqb, bq, nullptr, nullptr, qb, Hdim, Hdim, 1);
    gemm_bf16<<<ggrid, 256, GSM_TOT>>>(xb, wkb, bk, nullptr, nullptr, kb, Hdim, Hdim, 1);
    gemm_bf16<<<ggrid, 256, GSM_TOT>>>(xb, wvb, bv, nullptr, nullptr, vb, Hdim, Hdim, 0);

    // zero kv state (graph replays must be deterministic)
    const int kvn = Bsz * NHEAD * HDm * HDm;
    const int ksn = Bsz * NHEAD * HDm;
    zero_kernel<<<(kvn + 255) / 256, 256>>>(kv, kvn);
    zero_kernel<<<(ksn + 255) / 256, 256>>>(ksum, ksn);

    // kv state + ksum
    kv_accum<<<dim3(Bsz * NHEAD, 8), 256>>>(kb, vb, kv, ksum);

    // ctx -> bf16
    ctx_kernel<<<dim3(Bsz * NHEAD, Sseq / 128), 256>>>(qb, kv, ksum, cb);

    // output projection + bias + residual -> hs (f32)
    gemm_bf16<<<ggrid, 256, GSM_TOT>>>(cb, wdb, bd, x, hs, nullptr, Hdim, Hdim, 0);

    // LayerNorm
    ln_kernel<<<BSROWS, 256>>>(hs, gamma, beta, out);
}